// round 16
// baseline (speedup 1.0000x reference)
#include <cuda_runtime.h>
#include <cuda_bf16.h>
#include <float.h>
#include <stdint.h>

// ======================= scratch =======================
__device__ __nv_bfloat16 g_h1h[67108864];  // h1 channel-last hi [2][64][64][64][128]
__device__ __nv_bfloat16 g_h1l[67108864];
__device__ __nv_bfloat16 g_h2h[16777216];  // h2 channel-last [2][32^3][256]
__device__ __nv_bfloat16 g_h2l[16777216];
__device__ float g_h3[4194304];            // channel-last fp32, 2 partial halves
__device__ __nv_bfloat16 g_qh[2097152];    // quantized channel-last [2][16^3][256]
__device__ __nv_bfloat16 g_ql[2097152];
__device__ __nv_bfloat16 g_r1h[16777216];  // r1 channel-last [2][32^3][256]
__device__ __nv_bfloat16 g_r1l[16777216];
__device__ float g_r2[67108864];           // r2 channel-last fp32 [2][64^3][128]
__device__ int   g_idx[32768];
__device__ float g_weff[8192];
__device__ float g_bias_eff;
__device__ float g_partial[8192];
// prepped weights: [tap*CHK+chunk][hl][co][ci32] bf16  (CHK = CI/32)
__device__ __nv_bfloat16 g_w2p[4194304];   // w2 : CI=128, CO=256
__device__ __nv_bfloat16 g_w3p[16777216];  // w3 : CI=256, CO=256
__device__ __nv_bfloat16 g_d1p[16777216];  // dw1: CI=256, CO=256
__device__ __nv_bfloat16 g_d2p[8388608];   // dw2: CI=256, CO=128

// ======================= helpers =======================
__device__ __forceinline__ uint32_t smem_u32(const void* p) {
    uint32_t a;
    asm("{ .reg .u64 t; cvta.to.shared.u64 t, %1; cvt.u32.u64 %0, t; }" : "=r"(a) : "l"(p));
    return a;
}
__device__ __forceinline__ void ldsm_x4(uint32_t* r, uint32_t addr) {
    asm volatile("ldmatrix.sync.aligned.m8n8.x4.shared.b16 {%0,%1,%2,%3}, [%4];"
                 : "=r"(r[0]), "=r"(r[1]), "=r"(r[2]), "=r"(r[3]) : "r"(addr));
}
__device__ __forceinline__ void mma16816(float* d, const uint32_t* a,
                                         const uint32_t* b) {
    asm volatile(
        "mma.sync.aligned.m16n8k16.row.col.f32.bf16.bf16.f32 "
        "{%0,%1,%2,%3},{%4,%5,%6,%7},{%8,%9},{%0,%1,%2,%3};"
        : "+f"(d[0]), "+f"(d[1]), "+f"(d[2]), "+f"(d[3])
        : "r"(a[0]), "r"(a[1]), "r"(a[2]), "r"(a[3]), "r"(b[0]), "r"(b[1]));
}
__device__ __forceinline__ void cpa16(uint32_t dst, const void* src) {
    asm volatile("cp.async.cg.shared.global [%0], [%1], 16;" :: "r"(dst), "l"(src));
}
#define CP_COMMIT() asm volatile("cp.async.commit_group;" ::: "memory")
#define CP_WAIT(n)  asm volatile("cp.async.wait_group %0;" :: "n"(n) : "memory")

// swizzled chunk offset inside an 8KB plane: row in [0,128), chunk in [0,4)
__device__ __forceinline__ uint32_t swz(int row, int chunk) {
    return (uint32_t)(row * 64 + ((chunk ^ ((row >> 1) & 3)) << 4));
}

// ======================= conv1 (Ci=1, scalar) -> channel-last bf16 hi/lo =======================
__global__ void __launch_bounds__(256) conv1_kernel(
    const float* __restrict__ in, const float* __restrict__ w,
    const float* __restrict__ bias)
{
    __shared__ float sI[6 * 18 * 19];
    __shared__ float sW[64 * 64];
    const int t = threadIdx.x, b = blockIdx.z, coBase = blockIdx.y * 64;
    const int Din = 128;
    int bx = blockIdx.x & 7, tmp = blockIdx.x >> 3;
    int by = tmp & 7, bz = tmp >> 3;
    const int Z0 = bz * 2, Y0 = by * 8, X0 = bx * 8;
    const int coG = t >> 5, spG = t & 31;
    const int z = spG >> 4, y = (spG >> 1) & 7, xg = spG & 1;

    float acc[8][4];
#pragma unroll
    for (int j = 0; j < 8; j++)
#pragma unroll
        for (int i = 0; i < 4; i++) acc[j][i] = 0.f;

    const int gz0 = 2 * Z0 - 1, gy0 = 2 * Y0 - 1, gx0 = 2 * X0 - 1;
    const size_t DD = (size_t)Din * Din;

    for (int e = t; e < 6 * 18 * 18; e += 256) {
        int lx = e % 18; int r = e / 18;
        int ly = r % 18; int lz = r / 18;
        int gz = gz0 + lz, gy = gy0 + ly, gx = gx0 + lx;
        float v = 0.f;
        if ((unsigned)gz < (unsigned)Din && (unsigned)gy < (unsigned)Din &&
            (unsigned)gx < (unsigned)Din)
            v = in[(size_t)b * DD * Din + (size_t)gz * DD + (size_t)gy * Din + gx];
        sI[(lz * 18 + ly) * 19 + lx] = v;
    }
    for (int e = t; e < 64 * 64; e += 256) {
        int co = e >> 6;
        sW[e] = w[(size_t)(coBase + co) * 64 + (e & 63)];
    }
    __syncthreads();

    const float* sWc = sW + (coG * 8) * 64;
    for (int kz = 0; kz < 4; kz++)
        for (int ky = 0; ky < 4; ky++) {
            const float* rowI = sI + (2 * z + kz) * 342 + (2 * y + ky) * 19 + 8 * xg;
            const float* wT = sWc + kz * 16 + ky * 4;
#pragma unroll
            for (int kx = 0; kx < 4; kx++) {
                float i0 = rowI[kx], i1 = rowI[kx + 2], i2 = rowI[kx + 4], i3 = rowI[kx + 6];
#pragma unroll
                for (int j = 0; j < 8; j++) {
                    float wv = wT[j * 64 + kx];
                    acc[j][0] += wv * i0; acc[j][1] += wv * i1;
                    acc[j][2] += wv * i2; acc[j][3] += wv * i3;
                }
            }
        }

    float bv[8];
#pragma unroll
    for (int j = 0; j < 8; j++) bv[j] = bias[coBase + coG * 8 + j];
#pragma unroll
    for (int i = 0; i < 4; i++) {
        __nv_bfloat16 hp[8], lp[8];
#pragma unroll
        for (int j = 0; j < 8; j++) {
            float v = acc[j][i] + bv[j];
            v = v > 0.f ? v : 0.f;
            hp[j] = __float2bfloat16(v);
            lp[j] = __float2bfloat16(v - __bfloat162float(hp[j]));
        }
        size_t pos = ((((size_t)b * 64 + Z0 + z) * 64 + Y0 + y) * 64 + X0 + xg * 4 + i);
        size_t o = pos * 128 + coBase + coG * 8;
        *(uint4*)(g_h1h + o) = *(uint4*)hp;
        *(uint4*)(g_h1l + o) = *(uint4*)lp;
    }
}

// ======================= weight prep: -> [tc][hl][co][ci32] =======================
template<int CI, int CO, bool DECONV>
__global__ void __launch_bounds__(256) w_prep(const float* __restrict__ src,
                                              __nv_bfloat16* __restrict__ dst)
{
    size_t idx = (size_t)blockIdx.x * 256 + threadIdx.x;   // CI*CO*64 total
    int ci32 = idx & 31;
    int co = (int)((idx >> 5) % CO);
    int tc = (int)(idx / ((size_t)32 * CO));               // tap*CHK + chunk
    const int CHK = CI / 32;
    int chunk = tc % CHK, tap = tc / CHK;
    int ci = chunk * 32 + ci32;
    float v = DECONV ? src[((size_t)ci * CO + co) * 64 + tap]
                     : src[((size_t)co * CI + ci) * 64 + tap];
    __nv_bfloat16 hi = __float2bfloat16(v);
    __nv_bfloat16 lo = __float2bfloat16(v - __bfloat162float(hi));
    dst[((size_t)tc * 2 + 0) * CO * 32 + co * 32 + ci32] = hi;
    dst[((size_t)tc * 2 + 1) * CO * 32 + co * 32 + ci32] = lo;
}

// ======================= unified mma conv/deconv, K=32, 3-stage swizzled, 2 CTAs/SM =======================
// M=128 positions x N=128 co per CTA. One __syncthreads per iteration.
// CTA swizzle: coHalf / deconv parity class live in the LOW bits of blockIdx.x so
// CTAs sharing the same input region are scheduled adjacently (L2 dedup).
// OMODE: 0 fp32 NCDHW, 1 bf16 hi/lo channel-last, 2 fp32 channel-last
#define PLANE 8192
#define STAGE 32768
template<int CHK, int CO, bool DECONV, int OMODE, bool RELU, int TAPN, bool SPLIT>
__global__ void __launch_bounds__(256, 2) gemm_mma(
    const __nv_bfloat16* __restrict__ inH, const __nv_bfloat16* __restrict__ inL,
    const __nv_bfloat16* __restrict__ wp, const float* __restrict__ bias,
    float* __restrict__ outF, __nv_bfloat16* __restrict__ outH,
    __nv_bfloat16* __restrict__ outL, int Din, int G)
{
    extern __shared__ char smc[];
    const uint32_t sb = smem_u32(smc);
    float* sBias = (float*)(smc + 3 * STAGE);
    const int CI = CHK * 32;

    const int t = threadIdx.x, wid = t >> 5, lane = t & 31;

    // ---- block index decode (swizzled) ----
    int b, pz = 0, py = 0, px = 0, tap0 = 0, coHalf = 0, sp;
    bool zeroBias = false;
    {
        int bx = blockIdx.x;
        if (CO == 256) { coHalf = bx & 1; bx >>= 1; }
        if (DECONV) {
            int cls = bx & 7; bx >>= 3;
            pz = (cls >> 2) & 1; py = (cls >> 1) & 1; px = cls & 1;
            b = blockIdx.z;
        } else if (SPLIT) {
            b = blockIdx.z >> 1;
            int half = blockIdx.z & 1;
            tap0 = half * TAPN;
            outF += (size_t)half * 2097152;
            zeroBias = (half != 0);
        } else {
            b = blockIdx.z;
        }
        sp = bx;
    }
    if (t < 128) sBias[t] = zeroBias ? 0.f : bias[coHalf * 128 + t];

    const int nx = G >> 3;
    const int X0 = (sp % nx) * 8;
    const int Y0 = ((sp / nx) % nx) * 8;
    const int Z0 = (sp / (nx * nx)) * 2;

    float d[2][8][4];
#pragma unroll
    for (int mi = 0; mi < 2; mi++)
#pragma unroll
        for (int nj = 0; nj < 8; nj++)
#pragma unroll
            for (int k = 0; k < 4; k++) d[mi][nj][k] = 0.f;

    // A-load role
    const int arow = t >> 1, ahalf = t & 1;
    const int oz = Z0 + (arow >> 6), oy = Y0 + ((arow >> 3) & 7), ox = X0 + (arow & 7);
    const uint32_t aw0 = swz(arow, 2 * ahalf);
    const uint32_t aw1 = swz(arow, 2 * ahalf + 1);

    // B-fill role
    const uint32_t bw0 = swz(t >> 2, t & 3);
    const uint32_t bw1 = swz((t + 256) >> 2, (t + 256) & 3);

    // warp tile
    const int wm = wid & 3, wn = wid >> 2;
    const int laneR = lane & 15, laneQ = lane >> 4;
    const int bn = ((lane >> 4) << 3) + (lane & 7);
    const int bk = (lane >> 3) & 1;
    uint32_t aOffs[2][2], bOffs[4][2];
#pragma unroll
    for (int mi = 0; mi < 2; mi++) {
        int row = wm * 32 + mi * 16 + laneR;
#pragma unroll
        for (int k = 0; k < 2; k++) aOffs[mi][k] = swz(row, 2 * k + laneQ);
    }
#pragma unroll
    for (int np = 0; np < 4; np++) {
        int row = wn * 64 + np * 16 + bn;
#pragma unroll
        for (int k = 0; k < 2; k++) bOffs[np][k] = swz(row, 2 * k + bk);
    }

    const int NT = (DECONV ? 8 : TAPN) * CHK;

    auto fill = [&](int it, int s) {
        const int chunk = it % CHK;
        const int tt = it / CHK;
        int tap, zi, yi, xi;
        if (DECONV) {
            int jz = (tt >> 2) & 1, jy = (tt >> 1) & 1, jx = tt & 1;
            int kz = (1 - pz) + 2 * jz, ky = (1 - py) + 2 * jy, kx = (1 - px) + 2 * jx;
            tap = kz * 16 + ky * 4 + kx;
            zi = oz + (pz ? 1 - jz : -jz);
            yi = oy + (py ? 1 - jy : -jy);
            xi = ox + (px ? 1 - jx : -jx);
        } else {
            int tpp = tap0 + tt;
            int kz = tpp >> 4, ky = (tpp >> 2) & 3, kx = tpp & 3;
            tap = tpp;
            zi = 2 * oz + kz - 1; yi = 2 * oy + ky - 1; xi = 2 * ox + kx - 1;
        }
        const uint32_t base = sb + (uint32_t)s * STAGE;
        // ---- A ----
        {
            if ((unsigned)zi < (unsigned)Din && (unsigned)yi < (unsigned)Din &&
                (unsigned)xi < (unsigned)Din) {
                size_t src = ((((size_t)b * Din + zi) * Din + yi) * Din + xi) * CI +
                             chunk * 32 + ahalf * 16;
                const char* sh = (const char*)(inH + src);
                const char* sl = (const char*)(inL + src);
                cpa16(base + aw0, sh);
                cpa16(base + aw1, sh + 16);
                cpa16(base + PLANE + aw0, sl);
                cpa16(base + PLANE + aw1, sl + 16);
            } else {
                uint4 zv = make_uint4(0, 0, 0, 0);
                *(uint4*)(smc + (base - sb) + aw0) = zv;
                *(uint4*)(smc + (base - sb) + aw1) = zv;
                *(uint4*)(smc + (base - sb) + PLANE + aw0) = zv;
                *(uint4*)(smc + (base - sb) + PLANE + aw1) = zv;
            }
        }
        // ---- B ----
        {
            const int tc = tap * CHK + chunk;
            const char* bsH = (const char*)(wp + ((size_t)tc * 2 + 0) * CO * 32 +
                                            coHalf * 4096);
            const char* bsL = (const char*)(wp + ((size_t)tc * 2 + 1) * CO * 32 +
                                            coHalf * 4096);
            const uint32_t bHi = base + 2 * PLANE;
            cpa16(bHi + bw0, bsH + t * 16);
            cpa16(bHi + bw1, bsH + (t + 256) * 16);
            cpa16(bHi + PLANE + bw0, bsL + t * 16);
            cpa16(bHi + PLANE + bw1, bsL + (t + 256) * 16);
        }
    };

    fill(0, 0); CP_COMMIT();
    if (NT > 1) { fill(1, 1); CP_COMMIT(); }

    int s = 0;
    for (int it = 0; it < NT; it++) {
        if (it + 1 < NT) { CP_WAIT(1); } else { CP_WAIT(0); }
        __syncthreads();
        if (it + 2 < NT) {
            int s2 = s + 2; if (s2 >= 3) s2 -= 3;
            fill(it + 2, s2);
            CP_COMMIT();
        }

        const uint32_t base = sb + (uint32_t)s * STAGE;
        const uint32_t bbase = base + 2 * PLANE;
#pragma unroll
        for (int k = 0; k < 2; k++) {
            uint32_t afh[2][4], afl[2][4];
#pragma unroll
            for (int mi = 0; mi < 2; mi++) {
                ldsm_x4(afh[mi], base + aOffs[mi][k]);
                ldsm_x4(afl[mi], base + PLANE + aOffs[mi][k]);
            }
#pragma unroll
            for (int np = 0; np < 4; np++) {
                uint32_t bh[4], bl[4];
                ldsm_x4(bh, bbase + bOffs[np][k]);
                ldsm_x4(bl, bbase + PLANE + bOffs[np][k]);
#pragma unroll
                for (int mi = 0; mi < 2; mi++) {
                    mma16816(d[mi][2 * np],     afh[mi], bh);
                    mma16816(d[mi][2 * np + 1], afh[mi], bh + 2);
                    mma16816(d[mi][2 * np],     afh[mi], bl);
                    mma16816(d[mi][2 * np + 1], afh[mi], bl + 2);
                    mma16816(d[mi][2 * np],     afl[mi], bh);
                    mma16816(d[mi][2 * np + 1], afl[mi], bh + 2);
                }
            }
        }
        s = s + 1; if (s >= 3) s -= 3;
    }

    // ---- epilogue ----
    const int er = lane >> 2, ec = 2 * (lane & 3);
    const int ODim = DECONV ? 2 * G : G;
    const size_t OD3 = (size_t)ODim * ODim * ODim;
#pragma unroll
    for (int mi = 0; mi < 2; mi++) {
#pragma unroll
        for (int nj = 0; nj < 8; nj++) {
#pragma unroll
            for (int hh = 0; hh < 2; hh++) {
                int row = wm * 32 + mi * 16 + er + hh * 8;
                int col = wn * 64 + nj * 8 + ec;
                int zl = row >> 6, yl = (row >> 3) & 7, xl = row & 7;
                int ozo, oyo, oxo;
                if (DECONV) {
                    ozo = 2 * (Z0 + zl) + pz;
                    oyo = 2 * (Y0 + yl) + py;
                    oxo = 2 * (X0 + xl) + px;
                } else {
                    ozo = Z0 + zl; oyo = Y0 + yl; oxo = X0 + xl;
                }
                float v0 = d[mi][nj][2 * hh] + sBias[col];
                float v1 = d[mi][nj][2 * hh + 1] + sBias[col + 1];
                if (RELU) { v0 = v0 > 0.f ? v0 : 0.f; v1 = v1 > 0.f ? v1 : 0.f; }
                int co = coHalf * 128 + col;
                if (OMODE == 0) {
                    size_t o = ((size_t)(b * CO + co)) * OD3 +
                               (size_t)ozo * ODim * ODim + oyo * ODim + oxo;
                    outF[o] = v0;
                    outF[o + OD3] = v1;
                } else {
                    size_t pos = (((size_t)b * ODim + ozo) * ODim + oyo) * ODim + oxo;
                    if (OMODE == 2) {
                        float2 fv; fv.x = v0; fv.y = v1;
                        *(float2*)(outF + pos * CO + co) = fv;
                    } else {
                        __nv_bfloat16 h0 = __float2bfloat16(v0);
                        __nv_bfloat16 h1 = __float2bfloat16(v1);
                        __nv_bfloat162 hp; hp.x = h0; hp.y = h1;
                        __nv_bfloat162 lp;
                        lp.x = __float2bfloat16(v0 - __bfloat162float(h0));
                        lp.y = __float2bfloat16(v1 - __bfloat162float(h1));
                        *(__nv_bfloat162*)(outH + pos * CO + co) = hp;
                        *(__nv_bfloat162*)(outL + pos * CO + co) = lp;
                    }
                }
            }
        }
    }
}

// ======================= fold dw3 & wo =======================
__global__ void build_weff(const float* __restrict__ dw3, const float* __restrict__ db3,
                           const float* __restrict__ wo,  const float* __restrict__ bo)
{
    int t = blockIdx.x * 256 + threadIdx.x;
    if (t < 8192) {
        int ci = t >> 6, tap = t & 63;
        float s = 0.f;
        for (int co = 0; co < 128; co++)
            s += dw3[((size_t)(ci * 128 + co)) * 64 + tap] * wo[co];
        g_weff[t] = s;
    }
    if (t == 0) {
        float s = bo[0];
        for (int co = 0; co < 128; co++) s += db3[co] * wo[co];
        g_bias_eff = s;
    }
}

// ======================= fused deconv3 + 1x1: 2 outputs/thread =======================
__global__ void __launch_bounds__(256) fused_deconv3(float* __restrict__ out)
{
    __shared__ float sWe[8192];
    __shared__ float sI[8 * 4 * 6 * 10];   // [8ci][4z][6y][10x]
    const int t = threadIdx.x, b = blockIdx.z;
    int bx3 = blockIdx.x & 7, by = (blockIdx.x >> 3) & 15, bz = blockIdx.x >> 7;
    const int Z0 = bz * 4, Y0 = by * 8, X0 = bx3 * 16;
    const int z = t >> 6, y = (t >> 3) & 7, xg = t & 7;
    const int x0 = ((xg >> 1) << 2) + (xg & 1);   // local x: pair {x0, x0+2}

    for (int e = t; e < 8192; e += 256) sWe[e] = g_weff[e];

    const int kz0 = (z + 1) & 1, ky0 = (y + 1) & 1, kx0 = (x0 + 1) & 1;
    const int base_z = ((z + 1 - kz0) >> 1) + 1;
    const int base_y = ((y + 1 - ky0) >> 1) + 1;
    const int base_x = ((x0 + 1 - kx0) >> 1) + 1;
    const int iz0 = (Z0 >> 1) - 1, iy0 = (Y0 >> 1) - 1, ix0 = (X0 >> 1) - 1;

    float a0 = 0.f, a1 = 0.f;
    for (int ciBase = 0; ciBase < 128; ciBase += 8) {
        __syncthreads();
        for (int e = t; e < 8 * 4 * 6 * 10; e += 256) {
            int ci = e & 7;
            int pos = e >> 3;
            int lx = pos % 10; int r = pos / 10;
            int ly = r % 6; int lz = r / 6;
            int gz = iz0 + lz, gy = iy0 + ly, gx = ix0 + lx;
            float v = 0.f;
            if ((unsigned)gz < 64u && (unsigned)gy < 64u && (unsigned)gx < 64u)
                v = g_r2[((((size_t)b * 64 + gz) * 64 + gy) * 64 + gx) * 128 +
                         ciBase + ci];
            sI[((ci * 4 + lz) * 6 + ly) * 10 + lx] = v;
        }
        __syncthreads();
        for (int ci = 0; ci < 8; ci++) {
            const float* sIc = sI + ci * 240;
            const float* wc = sWe + (ciBase + ci) * 64;
#pragma unroll
            for (int a = 0; a < 2; a++)
#pragma unroll
            for (int bb = 0; bb < 2; bb++) {
                const float* row = sIc + (base_z - a) * 60 + (base_y - bb) * 10 + base_x;
                float ivm = row[-1], iv0 = row[0], ivp = row[1];
                int tapA = (kz0 + 2 * a) * 16 + (ky0 + 2 * bb) * 4 + kx0;
                float w0 = wc[tapA];
                float w1 = wc[tapA + 2];
                a0 += w0 * iv0 + w1 * ivm;
                a1 += w0 * ivp + w1 * iv0;
            }
        }
    }
    size_t obase = (size_t)b * 2097152 + (size_t)(Z0 + z) * 16384 + (Y0 + y) * 128 +
                   X0 + x0;
    out[obase] = a0 + g_bias_eff;
    out[obase + 2] = a1 + g_bias_eff;
}

// ======================= VQ: argmin + quantize + SSE partial (merged) =======================
__global__ void __launch_bounds__(256) vq_fused(const float* __restrict__ h3,
                                                const float* __restrict__ emb)
{
    __shared__ float sF[8][64];
    __shared__ float sE[64][65];
    __shared__ float sRed[8];
    const int t = threadIdx.x, r = t >> 5, tr = t & 31;
    const int n0 = blockIdx.x * 8;

    for (int e = t; e < 512; e += 256) {
        int rr = e >> 6, ee = e & 63;
        int n = n0 + rr;
        size_t o = (size_t)(n >> 2) * 256 + (n & 3) * 64 + ee;
        sF[rr][ee] = h3[o] + h3[o + 2097152];
    }
    float best = FLT_MAX; int bidx = 0;
    for (int kc = 0; kc < 512; kc += 64) {
        __syncthreads();
        for (int e = t; e < 4096; e += 256)
            sE[e >> 6][e & 63] = emb[(size_t)(kc + (e >> 6)) * 64 + (e & 63)];
        __syncthreads();
        float d1 = 0.f, d2 = 0.f;
        for (int e = 0; e < 64; e++) {
            float f = sF[r][e];
            float a = f - sE[tr][e];
            float c = f - sE[tr + 32][e];
            d1 += a * a; d2 += c * c;
        }
        if (d1 < best) { best = d1; bidx = kc + tr; }
        if (d2 < best) { best = d2; bidx = kc + tr + 32; }
    }
    for (int off = 16; off; off >>= 1) {
        float od = __shfl_down_sync(0xffffffffu, best, off);
        int   oi = __shfl_down_sync(0xffffffffu, bidx, off);
        if (od < best || (od == best && oi < bidx)) { best = od; bidx = oi; }
    }
    bidx = __shfl_sync(0xffffffffu, bidx, 0);
    const int n = n0 + r;
    if (tr == 0) g_idx[n] = bidx;

    // quantize + SSE for this row (64 channels, 2 per lane)
    float dsum = 0.f;
    size_t gbase = (size_t)(n >> 2) * 256 + (n & 3) * 64;
#pragma unroll
    for (int u = 0; u < 2; u++) {
        int e = tr + u * 32;
        float qv = emb[(size_t)bidx * 64 + e];
        __nv_bfloat16 hi = __float2bfloat16(qv);
        g_qh[gbase + e] = hi;
        g_ql[gbase + e] = __float2bfloat16(qv - __bfloat162float(hi));
        float dd = qv - sF[r][e];
        dsum += dd * dd;
    }
    for (int off = 16; off; off >>= 1)
        dsum += __shfl_down_sync(0xffffffffu, dsum, off);
    if (tr == 0) sRed[r] = dsum;
    __syncthreads();
    if (t == 0) {
        float s = 0.f;
#pragma unroll
        for (int k = 0; k < 8; k++) s += sRed[k];
        g_partial[blockIdx.x] = s;
    }
}

__global__ void __launch_bounds__(256) loss_final(float* __restrict__ out)
{
    __shared__ float sred[256];
    const int t = threadIdx.x;
    float s = 0.f;
    for (int k = 0; k < 16; k++) s += g_partial[t + 256 * k];
    sred[t] = s;
    __syncthreads();
    for (int st = 128; st; st >>= 1) { if (t < st) sred[t] += sred[t + st]; __syncthreads(); }
    if (t == 0) out[0] = sred[0] * 1.25f / 2097152.0f;
}

// ======================= launch =======================
extern "C" void kernel_launch(void* const* d_in, const int* in_sizes, int n_in,
                              void* d_out, int out_size)
{
    const float* x   = (const float*)d_in[0];
    const float* w1  = (const float*)d_in[1];
    const float* b1  = (const float*)d_in[2];
    const float* w2  = (const float*)d_in[3];
    const float* b2  = (const float*)d_in[4];
    const float* w3  = (const float*)d_in[5];
    const float* b3  = (const float*)d_in[6];
    const float* dw1 = (const float*)d_in[7];
    const float* db1 = (const float*)d_in[8];
    const float* dw2 = (const float*)d_in[9];
    const float* db2 = (const float*)d_in[10];
    const float* dw3 = (const float*)d_in[11];
    const float* db3 = (const float*)d_in[12];
    const float* wo  = (const float*)d_in[13];
    const float* bo  = (const float*)d_in[14];
    const float* emb = (const float*)d_in[15];
    float* out = (float*)d_out;

    float *h3, *r2;
    __nv_bfloat16 *h1h, *h1l, *h2h, *h2l, *qh, *ql, *r1h, *r1l;
    __nv_bfloat16 *w2p, *w3p, *d1p, *d2p;
    cudaGetSymbolAddress((void**)&h3, g_h3);
    cudaGetSymbolAddress((void**)&r2, g_r2);
    cudaGetSymbolAddress((void**)&h1h, g_h1h);
    cudaGetSymbolAddress((void**)&h1l, g_h1l);
    cudaGetSymbolAddress((void**)&h2h, g_h2h);
    cudaGetSymbolAddress((void**)&h2l, g_h2l);
    cudaGetSymbolAddress((void**)&qh, g_qh);
    cudaGetSymbolAddress((void**)&ql, g_ql);
    cudaGetSymbolAddress((void**)&r1h, g_r1h);
    cudaGetSymbolAddress((void**)&r1l, g_r1l);
    cudaGetSymbolAddress((void**)&w2p, g_w2p);
    cudaGetSymbolAddress((void**)&w3p, g_w3p);
    cudaGetSymbolAddress((void**)&d1p, g_d1p);
    cudaGetSymbolAddress((void**)&d2p, g_d2p);

    const int smem_mm = 3 * STAGE + 512;   // 98816 -> 2 CTAs/SM

    cudaFuncSetAttribute((const void*)gemm_mma<4, 256, false, 1, true, 64, false>,
                         cudaFuncAttributeMaxDynamicSharedMemorySize, smem_mm);
    cudaFuncSetAttribute((const void*)gemm_mma<8, 256, false, 2, false, 32, true>,
                         cudaFuncAttributeMaxDynamicSharedMemorySize, smem_mm);
    cudaFuncSetAttribute((const void*)gemm_mma<8, 256, true, 1, true, 64, false>,
                         cudaFuncAttributeMaxDynamicSharedMemorySize, smem_mm);
    cudaFuncSetAttribute((const void*)gemm_mma<8, 128, true, 2, true, 64, false>,
                         cudaFuncAttributeMaxDynamicSharedMemorySize, smem_mm);

    // ---- order chosen so conv2 gemm is launch #4 (profiler capture slot) ----
    w_prep<128, 256, false><<<8192, 256>>>(w2, w2p);                       // 1
    conv1_kernel<<<dim3(2048, 2, 2), 256>>>(x, w1, b1);                    // 2
    build_weff<<<32, 256>>>(dw3, db3, wo, bo);                             // 3
    // conv2: 256 spatial x 2 coHalf (LSB) per batch
    gemm_mma<4, 256, false, 1, true, 64, false><<<dim3(512, 1, 2), 256, smem_mm>>>(
        h1h, h1l, w2p, b2, nullptr, h2h, h2l, 64, 32);                     // 4
    w_prep<256, 256, false><<<16384, 256>>>(w3, w3p);                      // 5
    w_prep<256, 256, true ><<<16384, 256>>>(dw1, d1p);                     // 6
    w_prep<256, 128, true ><<<8192,  256>>>(dw2, d2p);                     // 7
    // conv3: 32 spatial x 2 coHalf; z = b*2 + tap-half
    gemm_mma<8, 256, false, 2, false, 32, true><<<dim3(64, 1, 4), 256, smem_mm>>>(
        h2h, h2l, w3p, b3, h3, nullptr, nullptr, 32, 16);                  // 8

    // ---- VQ (fused) + loss ----
    vq_fused<<<4096, 256>>>(h3, emb);
    loss_final<<<1, 256>>>(out);

    // ---- decoder ----
    // deconv1: 32 spatial x 8 cls x 2 coHalf
    gemm_mma<8, 256, true, 1, true, 64, false><<<dim3(512, 1, 2), 256, smem_mm>>>(
        qh, ql, d1p, db1, nullptr, r1h, r1l, 16, 16);
    // deconv2: 256 spatial x 8 cls
    gemm_mma<8, 128, true, 2, true, 64, false><<<dim3(2048, 1, 2), 256, smem_mm>>>(
        r1h, r1l, d2p, db2, r2, nullptr, nullptr, 32, 32);
    fused_deconv3<<<dim3(4096, 1, 2), 256>>>(out + 1);
}

// round 17
// speedup vs baseline: 1.0157x; 1.0157x over previous
#include <cuda_runtime.h>
#include <cuda_bf16.h>
#include <float.h>
#include <stdint.h>

// ======================= scratch =======================
__device__ __nv_bfloat16 g_h1h[67108864];  // h1 channel-last hi [2][64][64][64][128]
__device__ __nv_bfloat16 g_h1l[67108864];
__device__ __nv_bfloat16 g_h2h[16777216];  // h2 channel-last [2][32^3][256]
__device__ __nv_bfloat16 g_h2l[16777216];
__device__ float g_h3[4194304];            // channel-last fp32, 2 partial halves
__device__ __nv_bfloat16 g_qh[2097152];    // quantized channel-last [2][16^3][256]
__device__ __nv_bfloat16 g_ql[2097152];
__device__ __nv_bfloat16 g_r1h[16777216];  // r1 channel-last [2][32^3][256]
__device__ __nv_bfloat16 g_r1l[16777216];
__device__ float g_r2[67108864];           // r2 channel-last fp32 [2][64^3][128]
__device__ int   g_idx[32768];
__device__ float g_weff[8192];
__device__ float g_bias_eff;
__device__ float g_partial[8192];
// prepped weights: [tap*CHK+chunk][hl][co][ci32] bf16  (CHK = CI/32)
__device__ __nv_bfloat16 g_w2p[4194304];   // w2 : CI=128, CO=256
__device__ __nv_bfloat16 g_w3p[16777216];  // w3 : CI=256, CO=256
__device__ __nv_bfloat16 g_d1p[16777216];  // dw1: CI=256, CO=256
__device__ __nv_bfloat16 g_d2p[8388608];   // dw2: CI=256, CO=128

// ======================= helpers =======================
__device__ __forceinline__ uint32_t smem_u32(const void* p) {
    uint32_t a;
    asm("{ .reg .u64 t; cvta.to.shared.u64 t, %1; cvt.u32.u64 %0, t; }" : "=r"(a) : "l"(p));
    return a;
}
__device__ __forceinline__ void ldsm_x4(uint32_t* r, uint32_t addr) {
    asm volatile("ldmatrix.sync.aligned.m8n8.x4.shared.b16 {%0,%1,%2,%3}, [%4];"
                 : "=r"(r[0]), "=r"(r[1]), "=r"(r[2]), "=r"(r[3]) : "r"(addr));
}
__device__ __forceinline__ void mma16816(float* d, const uint32_t* a,
                                         const uint32_t* b) {
    asm volatile(
        "mma.sync.aligned.m16n8k16.row.col.f32.bf16.bf16.f32 "
        "{%0,%1,%2,%3},{%4,%5,%6,%7},{%8,%9},{%0,%1,%2,%3};"
        : "+f"(d[0]), "+f"(d[1]), "+f"(d[2]), "+f"(d[3])
        : "r"(a[0]), "r"(a[1]), "r"(a[2]), "r"(a[3]), "r"(b[0]), "r"(b[1]));
}
__device__ __forceinline__ void cpa16(uint32_t dst, const void* src) {
    asm volatile("cp.async.cg.shared.global [%0], [%1], 16;" :: "r"(dst), "l"(src));
}
#define CP_COMMIT() asm volatile("cp.async.commit_group;" ::: "memory")
#define CP_WAIT(n)  asm volatile("cp.async.wait_group %0;" :: "n"(n) : "memory")

// swizzled chunk offset inside an 8KB plane: row in [0,128), chunk in [0,4)
__device__ __forceinline__ uint32_t swz(int row, int chunk) {
    return (uint32_t)(row * 64 + ((chunk ^ ((row >> 1) & 3)) << 4));
}

// ======================= conv1 (Ci=1, scalar) -> channel-last bf16 hi/lo =======================
__global__ void __launch_bounds__(256) conv1_kernel(
    const float* __restrict__ in, const float* __restrict__ w,
    const float* __restrict__ bias)
{
    __shared__ float sI[6 * 18 * 19];
    __shared__ float sW[64 * 64];
    const int t = threadIdx.x, b = blockIdx.z, coBase = blockIdx.y * 64;
    const int Din = 128;
    int bx = blockIdx.x & 7, tmp = blockIdx.x >> 3;
    int by = tmp & 7, bz = tmp >> 3;
    const int Z0 = bz * 2, Y0 = by * 8, X0 = bx * 8;
    const int coG = t >> 5, spG = t & 31;
    const int z = spG >> 4, y = (spG >> 1) & 7, xg = spG & 1;

    float acc[8][4];
#pragma unroll
    for (int j = 0; j < 8; j++)
#pragma unroll
        for (int i = 0; i < 4; i++) acc[j][i] = 0.f;

    const int gz0 = 2 * Z0 - 1, gy0 = 2 * Y0 - 1, gx0 = 2 * X0 - 1;
    const size_t DD = (size_t)Din * Din;

    for (int e = t; e < 6 * 18 * 18; e += 256) {
        int lx = e % 18; int r = e / 18;
        int ly = r % 18; int lz = r / 18;
        int gz = gz0 + lz, gy = gy0 + ly, gx = gx0 + lx;
        float v = 0.f;
        if ((unsigned)gz < (unsigned)Din && (unsigned)gy < (unsigned)Din &&
            (unsigned)gx < (unsigned)Din)
            v = in[(size_t)b * DD * Din + (size_t)gz * DD + (size_t)gy * Din + gx];
        sI[(lz * 18 + ly) * 19 + lx] = v;
    }
    for (int e = t; e < 64 * 64; e += 256) {
        int co = e >> 6;
        sW[e] = w[(size_t)(coBase + co) * 64 + (e & 63)];
    }
    __syncthreads();

    const float* sWc = sW + (coG * 8) * 64;
    for (int kz = 0; kz < 4; kz++)
        for (int ky = 0; ky < 4; ky++) {
            const float* rowI = sI + (2 * z + kz) * 342 + (2 * y + ky) * 19 + 8 * xg;
            const float* wT = sWc + kz * 16 + ky * 4;
#pragma unroll
            for (int kx = 0; kx < 4; kx++) {
                float i0 = rowI[kx], i1 = rowI[kx + 2], i2 = rowI[kx + 4], i3 = rowI[kx + 6];
#pragma unroll
                for (int j = 0; j < 8; j++) {
                    float wv = wT[j * 64 + kx];
                    acc[j][0] += wv * i0; acc[j][1] += wv * i1;
                    acc[j][2] += wv * i2; acc[j][3] += wv * i3;
                }
            }
        }

    float bv[8];
#pragma unroll
    for (int j = 0; j < 8; j++) bv[j] = bias[coBase + coG * 8 + j];
#pragma unroll
    for (int i = 0; i < 4; i++) {
        __nv_bfloat16 hp[8], lp[8];
#pragma unroll
        for (int j = 0; j < 8; j++) {
            float v = acc[j][i] + bv[j];
            v = v > 0.f ? v : 0.f;
            hp[j] = __float2bfloat16(v);
            lp[j] = __float2bfloat16(v - __bfloat162float(hp[j]));
        }
        size_t pos = ((((size_t)b * 64 + Z0 + z) * 64 + Y0 + y) * 64 + X0 + xg * 4 + i);
        size_t o = pos * 128 + coBase + coG * 8;
        *(uint4*)(g_h1h + o) = *(uint4*)hp;
        *(uint4*)(g_h1l + o) = *(uint4*)lp;
    }
}

// ======================= weight prep: -> [tc][hl][co][ci32] =======================
template<int CI, int CO, bool DECONV>
__global__ void __launch_bounds__(256) w_prep(const float* __restrict__ src,
                                              __nv_bfloat16* __restrict__ dst)
{
    size_t idx = (size_t)blockIdx.x * 256 + threadIdx.x;   // CI*CO*64 total
    int ci32 = idx & 31;
    int co = (int)((idx >> 5) % CO);
    int tc = (int)(idx / ((size_t)32 * CO));               // tap*CHK + chunk
    const int CHK = CI / 32;
    int chunk = tc % CHK, tap = tc / CHK;
    int ci = chunk * 32 + ci32;
    float v = DECONV ? src[((size_t)ci * CO + co) * 64 + tap]
                     : src[((size_t)co * CI + ci) * 64 + tap];
    __nv_bfloat16 hi = __float2bfloat16(v);
    __nv_bfloat16 lo = __float2bfloat16(v - __bfloat162float(hi));
    dst[((size_t)tc * 2 + 0) * CO * 32 + co * 32 + ci32] = hi;
    dst[((size_t)tc * 2 + 1) * CO * 32 + co * 32 + ci32] = lo;
}

// ======================= unified mma conv/deconv, K=32, 3-stage swizzled, 2 CTAs/SM =======================
// M=128 positions x N=128 co per CTA. One __syncthreads per iteration.
// OMODE: 0 fp32 NCDHW, 1 bf16 hi/lo channel-last, 2 fp32 channel-last
#define PLANE 8192
#define STAGE 32768
template<int CHK, int CO, bool DECONV, int OMODE, bool RELU, int TAPN, bool SPLIT>
__global__ void __launch_bounds__(256, 2) gemm_mma(
    const __nv_bfloat16* __restrict__ inH, const __nv_bfloat16* __restrict__ inL,
    const __nv_bfloat16* __restrict__ wp, const float* __restrict__ bias,
    float* __restrict__ outF, __nv_bfloat16* __restrict__ outH,
    __nv_bfloat16* __restrict__ outL, int Din, int G)
{
    extern __shared__ char smc[];
    const uint32_t sb = smem_u32(smc);
    float* sBias = (float*)(smc + 3 * STAGE);
    const int CI = CHK * 32;

    const int t = threadIdx.x, wid = t >> 5, lane = t & 31;

    int b, pz = 0, py = 0, px = 0, tap0 = 0;
    if (DECONV) {
        int bz = blockIdx.z;
        b = bz >> 3;
        int cls = bz & 7;
        pz = (cls >> 2) & 1; py = (cls >> 1) & 1; px = cls & 1;
    } else if (SPLIT) {
        b = blockIdx.z >> 1;
        int half = blockIdx.z & 1;
        tap0 = half * TAPN;
        outF += (size_t)half * 2097152;
        if (t < 128) sBias[t] = half ? 0.f : bias[((CO == 256) ? blockIdx.y : 0) * 128 + t];
    } else {
        b = blockIdx.z;
    }
    const int coHalf = (CO == 256) ? blockIdx.y : 0;

    const int nx = G >> 3;
    const int X0 = (blockIdx.x % nx) * 8;
    const int Y0 = ((blockIdx.x / nx) % nx) * 8;
    const int Z0 = (blockIdx.x / (nx * nx)) * 2;

    if (!SPLIT && t < 128) sBias[t] = bias[coHalf * 128 + t];

    float d[2][8][4];
#pragma unroll
    for (int mi = 0; mi < 2; mi++)
#pragma unroll
        for (int nj = 0; nj < 8; nj++)
#pragma unroll
            for (int k = 0; k < 4; k++) d[mi][nj][k] = 0.f;

    // A-load role
    const int arow = t >> 1, ahalf = t & 1;
    const int oz = Z0 + (arow >> 6), oy = Y0 + ((arow >> 3) & 7), ox = X0 + (arow & 7);
    const uint32_t aw0 = swz(arow, 2 * ahalf);
    const uint32_t aw1 = swz(arow, 2 * ahalf + 1);

    // B-fill role
    const uint32_t bw0 = swz(t >> 2, t & 3);
    const uint32_t bw1 = swz((t + 256) >> 2, (t + 256) & 3);

    // warp tile
    const int wm = wid & 3, wn = wid >> 2;
    const int laneR = lane & 15, laneQ = lane >> 4;
    const int bn = ((lane >> 4) << 3) + (lane & 7);
    const int bk = (lane >> 3) & 1;
    uint32_t aOffs[2][2], bOffs[4][2];
#pragma unroll
    for (int mi = 0; mi < 2; mi++) {
        int row = wm * 32 + mi * 16 + laneR;
#pragma unroll
        for (int k = 0; k < 2; k++) aOffs[mi][k] = swz(row, 2 * k + laneQ);
    }
#pragma unroll
    for (int np = 0; np < 4; np++) {
        int row = wn * 64 + np * 16 + bn;
#pragma unroll
        for (int k = 0; k < 2; k++) bOffs[np][k] = swz(row, 2 * k + bk);
    }

    const int NT = (DECONV ? 8 : TAPN) * CHK;

    auto fill = [&](int it, int s) {
        const int chunk = it % CHK;
        const int tt = it / CHK;
        int tap, zi, yi, xi;
        if (DECONV) {
            int jz = (tt >> 2) & 1, jy = (tt >> 1) & 1, jx = tt & 1;
            int kz = (1 - pz) + 2 * jz, ky = (1 - py) + 2 * jy, kx = (1 - px) + 2 * jx;
            tap = kz * 16 + ky * 4 + kx;
            zi = oz + (pz ? 1 - jz : -jz);
            yi = oy + (py ? 1 - jy : -jy);
            xi = ox + (px ? 1 - jx : -jx);
        } else {
            int tpp = tap0 + tt;
            int kz = tpp >> 4, ky = (tpp >> 2) & 3, kx = tpp & 3;
            tap = tpp;
            zi = 2 * oz + kz - 1; yi = 2 * oy + ky - 1; xi = 2 * ox + kx - 1;
        }
        const uint32_t base = sb + (uint32_t)s * STAGE;
        // ---- A ----
        {
            if ((unsigned)zi < (unsigned)Din && (unsigned)yi < (unsigned)Din &&
                (unsigned)xi < (unsigned)Din) {
                size_t src = ((((size_t)b * Din + zi) * Din + yi) * Din + xi) * CI +
                             chunk * 32 + ahalf * 16;
                const char* sh = (const char*)(inH + src);
                const char* sl = (const char*)(inL + src);
                cpa16(base + aw0, sh);
                cpa16(base + aw1, sh + 16);
                cpa16(base + PLANE + aw0, sl);
                cpa16(base + PLANE + aw1, sl + 16);
            } else {
                uint4 zv = make_uint4(0, 0, 0, 0);
                *(uint4*)(smc + (base - sb) + aw0) = zv;
                *(uint4*)(smc + (base - sb) + aw1) = zv;
                *(uint4*)(smc + (base - sb) + PLANE + aw0) = zv;
                *(uint4*)(smc + (base - sb) + PLANE + aw1) = zv;
            }
        }
        // ---- B ----
        {
            const int tc = tap * CHK + chunk;
            const char* bsH = (const char*)(wp + ((size_t)tc * 2 + 0) * CO * 32 +
                                            coHalf * 4096);
            const char* bsL = (const char*)(wp + ((size_t)tc * 2 + 1) * CO * 32 +
                                            coHalf * 4096);
            const uint32_t bHi = base + 2 * PLANE;
            cpa16(bHi + bw0, bsH + t * 16);
            cpa16(bHi + bw1, bsH + (t + 256) * 16);
            cpa16(bHi + PLANE + bw0, bsL + t * 16);
            cpa16(bHi + PLANE + bw1, bsL + (t + 256) * 16);
        }
    };

    fill(0, 0); CP_COMMIT();
    if (NT > 1) { fill(1, 1); CP_COMMIT(); }

    int s = 0;
    for (int it = 0; it < NT; it++) {
        if (it + 1 < NT) { CP_WAIT(1); } else { CP_WAIT(0); }
        __syncthreads();
        if (it + 2 < NT) {
            int s2 = s + 2; if (s2 >= 3) s2 -= 3;
            fill(it + 2, s2);
            CP_COMMIT();
        }

        const uint32_t base = sb + (uint32_t)s * STAGE;
        const uint32_t bbase = base + 2 * PLANE;
#pragma unroll
        for (int k = 0; k < 2; k++) {
            uint32_t afh[2][4], afl[2][4];
#pragma unroll
            for (int mi = 0; mi < 2; mi++) {
                ldsm_x4(afh[mi], base + aOffs[mi][k]);
                ldsm_x4(afl[mi], base + PLANE + aOffs[mi][k]);
            }
#pragma unroll
            for (int np = 0; np < 4; np++) {
                uint32_t bh[4], bl[4];
                ldsm_x4(bh, bbase + bOffs[np][k]);
                ldsm_x4(bl, bbase + PLANE + bOffs[np][k]);
#pragma unroll
                for (int mi = 0; mi < 2; mi++) {
                    mma16816(d[mi][2 * np],     afh[mi], bh);
                    mma16816(d[mi][2 * np + 1], afh[mi], bh + 2);
                    mma16816(d[mi][2 * np],     afh[mi], bl);
                    mma16816(d[mi][2 * np + 1], afh[mi], bl + 2);
                    mma16816(d[mi][2 * np],     afl[mi], bh);
                    mma16816(d[mi][2 * np + 1], afl[mi], bh + 2);
                }
            }
        }
        s = s + 1; if (s >= 3) s -= 3;
    }

    // ---- epilogue ----
    const int er = lane >> 2, ec = 2 * (lane & 3);
    const int ODim = DECONV ? 2 * G : G;
    const size_t OD3 = (size_t)ODim * ODim * ODim;
#pragma unroll
    for (int mi = 0; mi < 2; mi++) {
#pragma unroll
        for (int nj = 0; nj < 8; nj++) {
#pragma unroll
            for (int hh = 0; hh < 2; hh++) {
                int row = wm * 32 + mi * 16 + er + hh * 8;
                int col = wn * 64 + nj * 8 + ec;
                int zl = row >> 6, yl = (row >> 3) & 7, xl = row & 7;
                int ozo, oyo, oxo;
                if (DECONV) {
                    ozo = 2 * (Z0 + zl) + pz;
                    oyo = 2 * (Y0 + yl) + py;
                    oxo = 2 * (X0 + xl) + px;
                } else {
                    ozo = Z0 + zl; oyo = Y0 + yl; oxo = X0 + xl;
                }
                float v0 = d[mi][nj][2 * hh] + sBias[col];
                float v1 = d[mi][nj][2 * hh + 1] + sBias[col + 1];
                if (RELU) { v0 = v0 > 0.f ? v0 : 0.f; v1 = v1 > 0.f ? v1 : 0.f; }
                int co = coHalf * 128 + col;
                if (OMODE == 0) {
                    size_t o = ((size_t)(b * CO + co)) * OD3 +
                               (size_t)ozo * ODim * ODim + oyo * ODim + oxo;
                    outF[o] = v0;
                    outF[o + OD3] = v1;
                } else {
                    size_t pos = (((size_t)b * ODim + ozo) * ODim + oyo) * ODim + oxo;
                    if (OMODE == 2) {
                        float2 fv; fv.x = v0; fv.y = v1;
                        *(float2*)(outF + pos * CO + co) = fv;
                    } else {
                        __nv_bfloat16 h0 = __float2bfloat16(v0);
                        __nv_bfloat16 h1 = __float2bfloat16(v1);
                        __nv_bfloat162 hp; hp.x = h0; hp.y = h1;
                        __nv_bfloat162 lp;
                        lp.x = __float2bfloat16(v0 - __bfloat162float(h0));
                        lp.y = __float2bfloat16(v1 - __bfloat162float(h1));
                        *(__nv_bfloat162*)(outH + pos * CO + co) = hp;
                        *(__nv_bfloat162*)(outL + pos * CO + co) = lp;
                    }
                }
            }
        }
    }
}

// ======================= fold dw3 & wo =======================
__global__ void build_weff(const float* __restrict__ dw3, const float* __restrict__ db3,
                           const float* __restrict__ wo,  const float* __restrict__ bo)
{
    int t = blockIdx.x * 256 + threadIdx.x;
    if (t < 8192) {
        int ci = t >> 6, tap = t & 63;
        float s = 0.f;
        for (int co = 0; co < 128; co++)
            s += dw3[((size_t)(ci * 128 + co)) * 64 + tap] * wo[co];
        g_weff[t] = s;
    }
    if (t == 0) {
        float s = bo[0];
        for (int co = 0; co < 128; co++) s += db3[co] * wo[co];
        g_bias_eff = s;
    }
}

// ======================= fused deconv3 + 1x1: 2 outputs/thread =======================
__global__ void __launch_bounds__(256) fused_deconv3(float* __restrict__ out)
{
    __shared__ float sWe[8192];
    __shared__ float sI[8 * 4 * 6 * 10];   // [8ci][4z][6y][10x]
    const int t = threadIdx.x, b = blockIdx.z;
    int bx3 = blockIdx.x & 7, by = (blockIdx.x >> 3) & 15, bz = blockIdx.x >> 7;
    const int Z0 = bz * 4, Y0 = by * 8, X0 = bx3 * 16;
    const int z = t >> 6, y = (t >> 3) & 7, xg = t & 7;
    const int x0 = ((xg >> 1) << 2) + (xg & 1);   // local x: pair {x0, x0+2}

    for (int e = t; e < 8192; e += 256) sWe[e] = g_weff[e];

    const int kz0 = (z + 1) & 1, ky0 = (y + 1) & 1, kx0 = (x0 + 1) & 1;
    const int base_z = ((z + 1 - kz0) >> 1) + 1;
    const int base_y = ((y + 1 - ky0) >> 1) + 1;
    const int base_x = ((x0 + 1 - kx0) >> 1) + 1;
    const int iz0 = (Z0 >> 1) - 1, iy0 = (Y0 >> 1) - 1, ix0 = (X0 >> 1) - 1;

    float a0 = 0.f, a1 = 0.f;
    for (int ciBase = 0; ciBase < 128; ciBase += 8) {
        __syncthreads();
        for (int e = t; e < 8 * 4 * 6 * 10; e += 256) {
            int ci = e & 7;
            int pos = e >> 3;
            int lx = pos % 10; int r = pos / 10;
            int ly = r % 6; int lz = r / 6;
            int gz = iz0 + lz, gy = iy0 + ly, gx = ix0 + lx;
            float v = 0.f;
            if ((unsigned)gz < 64u && (unsigned)gy < 64u && (unsigned)gx < 64u)
                v = g_r2[((((size_t)b * 64 + gz) * 64 + gy) * 64 + gx) * 128 +
                         ciBase + ci];
            sI[((ci * 4 + lz) * 6 + ly) * 10 + lx] = v;
        }
        __syncthreads();
        for (int ci = 0; ci < 8; ci++) {
            const float* sIc = sI + ci * 240;
            const float* wc = sWe + (ciBase + ci) * 64;
#pragma unroll
            for (int a = 0; a < 2; a++)
#pragma unroll
            for (int bb = 0; bb < 2; bb++) {
                const float* row = sIc + (base_z - a) * 60 + (base_y - bb) * 10 + base_x;
                float ivm = row[-1], iv0 = row[0], ivp = row[1];
                int tapA = (kz0 + 2 * a) * 16 + (ky0 + 2 * bb) * 4 + kx0;
                float w0 = wc[tapA];
                float w1 = wc[tapA + 2];
                a0 += w0 * iv0 + w1 * ivm;
                a1 += w0 * ivp + w1 * iv0;
            }
        }
    }
    size_t obase = (size_t)b * 2097152 + (size_t)(Z0 + z) * 16384 + (Y0 + y) * 128 +
                   X0 + x0;
    out[obase] = a0 + g_bias_eff;
    out[obase + 2] = a1 + g_bias_eff;
}

// ======================= VQ: argmin + quantize + SSE partial (merged) =======================
__global__ void __launch_bounds__(256) vq_fused(const float* __restrict__ h3,
                                                const float* __restrict__ emb)
{
    __shared__ float sF[8][64];
    __shared__ float sE[64][65];
    __shared__ float sRed[8];
    const int t = threadIdx.x, r = t >> 5, tr = t & 31;
    const int n0 = blockIdx.x * 8;

    for (int e = t; e < 512; e += 256) {
        int rr = e >> 6, ee = e & 63;
        int n = n0 + rr;
        size_t o = (size_t)(n >> 2) * 256 + (n & 3) * 64 + ee;
        sF[rr][ee] = h3[o] + h3[o + 2097152];
    }
    float best = FLT_MAX; int bidx = 0;
    for (int kc = 0; kc < 512; kc += 64) {
        __syncthreads();
        for (int e = t; e < 4096; e += 256)
            sE[e >> 6][e & 63] = emb[(size_t)(kc + (e >> 6)) * 64 + (e & 63)];
        __syncthreads();
        float d1 = 0.f, d2 = 0.f;
        for (int e = 0; e < 64; e++) {
            float f = sF[r][e];
            float a = f - sE[tr][e];
            float c = f - sE[tr + 32][e];
            d1 += a * a; d2 += c * c;
        }
        if (d1 < best) { best = d1; bidx = kc + tr; }
        if (d2 < best) { best = d2; bidx = kc + tr + 32; }
    }
    for (int off = 16; off; off >>= 1) {
        float od = __shfl_down_sync(0xffffffffu, best, off);
        int   oi = __shfl_down_sync(0xffffffffu, bidx, off);
        if (od < best || (od == best && oi < bidx)) { best = od; bidx = oi; }
    }
    bidx = __shfl_sync(0xffffffffu, bidx, 0);
    const int n = n0 + r;
    if (tr == 0) g_idx[n] = bidx;

    // quantize + SSE for this row (64 channels, 2 per lane)
    float dsum = 0.f;
    size_t gbase = (size_t)(n >> 2) * 256 + (n & 3) * 64;
#pragma unroll
    for (int u = 0; u < 2; u++) {
        int e = tr + u * 32;
        float qv = emb[(size_t)bidx * 64 + e];
        __nv_bfloat16 hi = __float2bfloat16(qv);
        g_qh[gbase + e] = hi;
        g_ql[gbase + e] = __float2bfloat16(qv - __bfloat162float(hi));
        float dd = qv - sF[r][e];
        dsum += dd * dd;
    }
    for (int off = 16; off; off >>= 1)
        dsum += __shfl_down_sync(0xffffffffu, dsum, off);
    if (tr == 0) sRed[r] = dsum;
    __syncthreads();
    if (t == 0) {
        float s = 0.f;
#pragma unroll
        for (int k = 0; k < 8; k++) s += sRed[k];
        g_partial[blockIdx.x] = s;
    }
}

__global__ void __launch_bounds__(256) loss_final(float* __restrict__ out)
{
    __shared__ float sred[256];
    const int t = threadIdx.x;
    float s = 0.f;
    for (int k = 0; k < 16; k++) s += g_partial[t + 256 * k];
    sred[t] = s;
    __syncthreads();
    for (int st = 128; st; st >>= 1) { if (t < st) sred[t] += sred[t + st]; __syncthreads(); }
    if (t == 0) out[0] = sred[0] * 1.25f / 2097152.0f;
}

// ======================= launch =======================
extern "C" void kernel_launch(void* const* d_in, const int* in_sizes, int n_in,
                              void* d_out, int out_size)
{
    const float* x   = (const float*)d_in[0];
    const float* w1  = (const float*)d_in[1];
    const float* b1  = (const float*)d_in[2];
    const float* w2  = (const float*)d_in[3];
    const float* b2  = (const float*)d_in[4];
    const float* w3  = (const float*)d_in[5];
    const float* b3  = (const float*)d_in[6];
    const float* dw1 = (const float*)d_in[7];
    const float* db1 = (const float*)d_in[8];
    const float* dw2 = (const float*)d_in[9];
    const float* db2 = (const float*)d_in[10];
    const float* dw3 = (const float*)d_in[11];
    const float* db3 = (const float*)d_in[12];
    const float* wo  = (const float*)d_in[13];
    const float* bo  = (const float*)d_in[14];
    const float* emb = (const float*)d_in[15];
    float* out = (float*)d_out;

    float *h3, *r2;
    __nv_bfloat16 *h1h, *h1l, *h2h, *h2l, *qh, *ql, *r1h, *r1l;
    __nv_bfloat16 *w2p, *w3p, *d1p, *d2p;
    cudaGetSymbolAddress((void**)&h3, g_h3);
    cudaGetSymbolAddress((void**)&r2, g_r2);
    cudaGetSymbolAddress((void**)&h1h, g_h1h);
    cudaGetSymbolAddress((void**)&h1l, g_h1l);
    cudaGetSymbolAddress((void**)&h2h, g_h2h);
    cudaGetSymbolAddress((void**)&h2l, g_h2l);
    cudaGetSymbolAddress((void**)&qh, g_qh);
    cudaGetSymbolAddress((void**)&ql, g_ql);
    cudaGetSymbolAddress((void**)&r1h, g_r1h);
    cudaGetSymbolAddress((void**)&r1l, g_r1l);
    cudaGetSymbolAddress((void**)&w2p, g_w2p);
    cudaGetSymbolAddress((void**)&w3p, g_w3p);
    cudaGetSymbolAddress((void**)&d1p, g_d1p);
    cudaGetSymbolAddress((void**)&d2p, g_d2p);

    const int smem_mm = 3 * STAGE + 512;   // 98816 -> 2 CTAs/SM

    cudaFuncSetAttribute((const void*)gemm_mma<4, 256, false, 1, true, 64, false>,
                         cudaFuncAttributeMaxDynamicSharedMemorySize, smem_mm);
    cudaFuncSetAttribute((const void*)gemm_mma<8, 256, false, 2, false, 32, true>,
                         cudaFuncAttributeMaxDynamicSharedMemorySize, smem_mm);
    cudaFuncSetAttribute((const void*)gemm_mma<8, 256, true, 1, true, 64, false>,
                         cudaFuncAttributeMaxDynamicSharedMemorySize, smem_mm);
    cudaFuncSetAttribute((const void*)gemm_mma<8, 128, true, 2, true, 64, false>,
                         cudaFuncAttributeMaxDynamicSharedMemorySize, smem_mm);

    // ---- order chosen so conv2 gemm is launch #4 (profiler capture slot) ----
    w_prep<128, 256, false><<<8192, 256>>>(w2, w2p);                       // 1
    conv1_kernel<<<dim3(2048, 2, 2), 256>>>(x, w1, b1);                    // 2
    build_weff<<<32, 256>>>(dw3, db3, wo, bo);                             // 3
    gemm_mma<4, 256, false, 1, true, 64, false><<<dim3(256, 2, 2), 256, smem_mm>>>(
        h1h, h1l, w2p, b2, nullptr, h2h, h2l, 64, 32);                     // 4: conv2
    w_prep<256, 256, false><<<16384, 256>>>(w3, w3p);                      // 5
    w_prep<256, 256, true ><<<16384, 256>>>(dw1, d1p);                     // 6
    w_prep<256, 128, true ><<<8192,  256>>>(dw2, d2p);                     // 7
    // conv3: split taps across 2 halves -> partial sums (channel-last fp32)
    gemm_mma<8, 256, false, 2, false, 32, true><<<dim3(32, 2, 4), 256, smem_mm>>>(
        h2h, h2l, w3p, b3, h3, nullptr, nullptr, 32, 16);                  // 8

    // ---- VQ (fused) + loss ----
    vq_fused<<<4096, 256>>>(h3, emb);
    loss_final<<<1, 256>>>(out);

    // ---- decoder ----
    gemm_mma<8, 256, true, 1, true, 64, false><<<dim3(32, 2, 16), 256, smem_mm>>>(
        qh, ql, d1p, db1, nullptr, r1h, r1l, 16, 16);
    gemm_mma<8, 128, true, 2, true, 64, false><<<dim3(256, 1, 16), 256, smem_mm>>>(
        r1h, r1l, d2p, db2, r2, nullptr, nullptr, 32, 32);
    fused_deconv3<<<dim3(4096, 1, 2), 256>>>(out + 1);
}